// round 6
// baseline (speedup 1.0000x reference)
#include <cuda_runtime.h>
#include <cuda_bf16.h>
#include <cstdint>

#define NB   64
#define CC   64
#define TT   256
#define VV   25

typedef unsigned long long ull;

// ---------------- scratch (static device memory) ----------------
__device__ __align__(16) __nv_bfloat16 g_W9b[9 * 128 * 64];  // [tap][ch][cin]
__device__ __align__(16) __nv_bfloat16 g_W1b[160 * 64];      // [ch][cin]
__device__ float g_b9[128];
__device__ float g_b1[160];
__device__ float g_Acomb[625];
__device__ float g_Gram[64 * 9 * 625];
__device__ float g_A1[64 * 3 * 625];
__device__ float g_WdS[192 * 64];
__device__ float g_bd2[64];

// branch tables
__constant__ int c_i9[8]  = {0,0,1,1,1,1,2,2};
__constant__ int c_s9[8]  = {0,1,0,1,2,3,0,1};
__constant__ int c_i1[10] = {0,0,0,0,1,1,2,2,2,2};
__constant__ int c_s1[10] = {0,1,2,3,0,1,0,1,2,3};
__constant__ int c_gi9[4] = {0,1,1,2};
__constant__ int c_gj9[4] = {1,1,2,1};
__constant__ int c_gi1[5] = {0,0,1,2,2};
__constant__ int c_gj1[5] = {0,2,0,0,2};

// ---------------- f32x2 helpers ----------------
__device__ __forceinline__ ull pack2(float lo, float hi) {
    ull r; asm("mov.b64 %0, {%1,%2};" : "=l"(r) : "f"(lo), "f"(hi)); return r;
}
__device__ __forceinline__ void fma2(ull& d, ull a, ull b) {
    asm("fma.rn.f32x2 %0, %1, %2, %0;" : "+l"(d) : "l"(a), "l"(b));
}
__device__ __forceinline__ float2 unpack2(ull p) {
    float2 f; asm("mov.b64 {%0,%1}, %2;" : "=f"(f.x), "=f"(f.y) : "l"(p)); return f;
}

// ---------------- mma.sync m16n8k16 bf16 (sm_80+, compute_103-safe) --------
__device__ __forceinline__ void mma_bf16(float* d, uint32_t a0, uint32_t a1,
                                         uint32_t a2, uint32_t a3,
                                         uint32_t b0, uint32_t b1) {
    asm volatile(
        "mma.sync.aligned.m16n8k16.row.col.f32.bf16.bf16.f32 "
        "{%0,%1,%2,%3}, {%4,%5,%6,%7}, {%8,%9}, {%0,%1,%2,%3};"
        : "+f"(d[0]), "+f"(d[1]), "+f"(d[2]), "+f"(d[3])
        : "r"(a0), "r"(a1), "r"(a2), "r"(a3), "r"(b0), "r"(b1));
}

// ---------------- kernel 0: prep ----------------
__global__ void prep_kernel(const float* __restrict__ weights, const float* __restrict__ A,
                            const float* __restrict__ Wa, const float* __restrict__ ba,
                            const float* __restrict__ Wb, const float* __restrict__ bb,
                            const float* __restrict__ WT1, const float* __restrict__ bT1,
                            const float* __restrict__ WT2, const float* __restrict__ bT2,
                            const float* __restrict__ WST11, const float* __restrict__ bST11,
                            const float* __restrict__ WST12, const float* __restrict__ bST12,
                            const float* __restrict__ Wd, const float* __restrict__ bd,
                            const float* __restrict__ gamma, const float* __restrict__ beta,
                            const float* __restrict__ mean, const float* __restrict__ var) {
    __shared__ float sA[625], sA4[625];
    const int tid = threadIdx.x;
    if (tid < 625) {
        float a = A[tid];
        sA[tid] = a;
        int v = tid / 25, w = tid % 25;
        float a2 = a * a;  // elementwise Chebyshev (torch.pow semantics)
        sA4[tid] = 8.f * a2 * a2 - 8.f * a2 + (v == w ? 1.f : 0.f);
    }
    __syncthreads();
    if (tid < 25) {
        const int w = tid;
        float w0 = weights[0], w1 = weights[1];
        float m = -1e30f;
        for (int v = 0; v < 25; ++v) m = fmaxf(m, sA4[v*25+w] * 0.04f);
        float ssum = 0.f;
        for (int v = 0; v < 25; ++v) ssum += expf(sA4[v*25+w] * 0.04f - m);
        float inv = 1.f / ssum;
        for (int v = 0; v < 25; ++v)
            g_Acomb[v*25+w] = w0 * sA[v*25+w] + w1 * expf(sA4[v*25+w] * 0.04f - m) * inv;
    }
    // 9-tap weights bf16: [tap][128 ch][64 cin]
    for (int idx = tid; idx < 9 * 128 * 64; idx += blockDim.x) {
        int tap = idx / 8192, r = idx % 8192;
        int m = r / 64, c = r % 64;
        int g = m >> 4;
        int i = c_i9[g], s = c_s9[g];
        const float* W = (s == 0) ? WT1 : (s == 1) ? WT2 : (s == 2) ? WST11 : WST12;
        g_W9b[idx] = __float2bfloat16(W[((i*16 + (m & 15))*64 + c)*9 + tap]);
    }
    for (int idx = tid; idx < 128; idx += blockDim.x) {
        int g = idx >> 4, c = idx & 15;
        int i = c_i9[g], s = c_s9[g];
        const float* B = (s == 0) ? bT1 : (s == 1) ? bT2 : (s == 2) ? bST11 : bST12;
        g_b9[idx] = B[i*16 + c];
    }
    // 1x1 weights bf16: [160 ch][64 cin]
    for (int idx = tid; idx < 160 * 64; idx += blockDim.x) {
        int m = idx / 64, c = idx % 64;
        int g = m >> 4;
        int i = c_i1[g], s = c_s1[g];
        float val;
        if (s == 0)      val = Wa[(i*16 + (m & 15))*64 + c];
        else if (s == 1) val = Wb[(i*16 + (m & 15))*64 + c];
        else if (s == 2) val = WST11[((i*16 + (m & 15))*64 + c)*9 + 4];
        else             val = WST12[((i*16 + (m & 15))*64 + c)*9 + 4];
        g_W1b[idx] = __float2bfloat16(val);
    }
    for (int idx = tid; idx < 160; idx += blockDim.x) {
        int g = idx >> 4, c = idx & 15;
        int i = c_i1[g], s = c_s1[g];
        const float* B = (s == 0) ? ba : (s == 1) ? bb : (s == 2) ? bST11 : bST12;
        g_b1[idx] = B[i*16 + c];
    }
    for (int idx = tid; idx < 192 * 64; idx += blockDim.x) {
        int k = idx / 64, o = idx % 64;
        int i = k / 64, c = k % 64;
        float sc = gamma[o] * rsqrtf(var[o] + 1e-5f);
        g_WdS[idx] = Wd[(i * 64 + o) * 64 + c] * sc;
    }
    for (int o = tid; o < 64; o += blockDim.x) {
        float sc = gamma[o] * rsqrtf(var[o] + 1e-5f);
        g_bd2[o] = (bd[o] + bd[64 + o] + bd[128 + o] - mean[o]) * sc + beta[o];
    }
}

// ---------------- kernel 1: unified conv (mma.sync bf16) + fused gram ------
// grid (32 t-blocks of 8, 64 n), 512 thr = 16 warps.
// xs: [n=512 rows (16 tsl x 32 v)][66 cin-pad] bf16 (stride 66 -> conflict-free)
// fT: [18 br][25 v][132 kpad] bf16, k = (ch%16)*8 + tt
#define XS_N_STRIDE 66
#define XS_BF16     (512 * XS_N_STRIDE)            // 33792
#define FT_BF16     (18 * 25 * 132)                // 59400
#define SMEM_CONV   ((XS_BF16 + FT_BF16) * 2)      // 186384 B

struct JobDesc { int strip; int half; int is9; };

__global__ void __launch_bounds__(512, 1) convm_kernel(const float* __restrict__ x) {
    extern __shared__ __nv_bfloat16 smb[];
    __nv_bfloat16* xs = smb;
    __nv_bfloat16* fT = smb + XS_BF16;
    const int n = blockIdx.y, t0 = blockIdx.x * 8;
    const int tid = threadIdx.x, warp = tid >> 5, lane = tid & 31;

    // zero xs, then fill valid region
    {
        uint32_t* xz = (uint32_t*)xs;
        for (int i = tid; i < XS_BF16 / 2; i += 512) xz[i] = 0u;
    }
    __syncthreads();
    {
        const float* xn = x + (size_t)n * (CC * TT * VV);
        for (int idx = tid; idx < 64 * 16 * 25; idx += 512) {
            int cin = idx / 400, r = idx % 400;
            int tsl = r / 25, v = r % 25;
            int t = t0 - 4 + tsl;
            if (t < 0 || t >= TT) continue;
            xs[(tsl * 32 + v) * XS_N_STRIDE + cin] =
                __float2bfloat16(xn[(cin * TT + t) * VV + v]);
        }
    }
    __syncthreads();

    // jobs: job0 = conv9 (all warps), job1 = conv1 strips 8..15 (all),
    //       job2 = conv1 strips 16..17 (warps 0..3)
    const int row = lane >> 2;           // also B col offset
    const int kq  = (lane & 3) * 2;
    float acc[16][4];

    for (int job = 0; job < 3; ++job) {
        if (job == 2 && warp >= 4) break;
        const int strip = (job == 0) ? (warp >> 1) : (job == 1) ? 8 + (warp >> 1)
                                                                : 16 + (warp >> 1);
        const int half = warp & 1;
        const int is9 = (job == 0);
#pragma unroll
        for (int a = 0; a < 16; ++a)
#pragma unroll
            for (int b = 0; b < 4; ++b) acc[a][b] = 0.f;

        const int ntaps = is9 ? 9 : 1;
        for (int jt = 0; jt < ntaps; ++jt) {
            const int tap = is9 ? jt : 4;
            const __nv_bfloat16* Ab = is9 ? g_W9b + (size_t)(tap * 128 + strip * 16) * 64
                                          : g_W1b + (size_t)(strip - 8) * 16 * 64;
            const __nv_bfloat16* xb = xs + (size_t)(tap * 32 + half * 128 + row) * XS_N_STRIDE;
#pragma unroll
            for (int k0 = 0; k0 < 64; k0 += 16) {
                uint32_t a0 = *(const uint32_t*)(Ab + row * 64 + k0 + kq);
                uint32_t a1 = *(const uint32_t*)(Ab + (row + 8) * 64 + k0 + kq);
                uint32_t a2 = *(const uint32_t*)(Ab + row * 64 + k0 + kq + 8);
                uint32_t a3 = *(const uint32_t*)(Ab + (row + 8) * 64 + k0 + kq + 8);
#pragma unroll
                for (int nt = 0; nt < 16; ++nt) {
                    uint32_t b0 = *(const uint32_t*)(xb + nt * 8 * XS_N_STRIDE + k0 + kq);
                    uint32_t b1 = *(const uint32_t*)(xb + nt * 8 * XS_N_STRIDE + k0 + kq + 8);
                    mma_bf16(acc[nt], a0, a1, a2, a3, b0, b1);
                }
            }
        }
        // epilogue: bias + bf16 store into fT
        const float* bias_arr = is9 ? g_b9 + strip * 16 : g_b1 + (strip - 8) * 16;
        const float bias_lo = bias_arr[row];
        const float bias_hi = bias_arr[row + 8];
#pragma unroll
        for (int nt = 0; nt < 16; ++nt)
#pragma unroll
            for (int j = 0; j < 4; ++j) {
                const int ch = row + ((j >= 2) ? 8 : 0);
                const int nl = half * 128 + nt * 8 + (lane & 3) * 2 + (j & 1);
                const int tt = nl >> 5, v = nl & 31;
                if (v < 25)
                    fT[(strip * 25 + v) * 132 + ch * 8 + tt] =
                        __float2bfloat16(acc[nt][j] + ((j >= 2) ? bias_hi : bias_lo));
            }
    }
    __syncthreads();

    // gram: 450 workers = 9 pairs x 25 cells x 2 k-halves (k=64 each)
    if (tid < 450) {
        const int pair = tid / 50, rem = tid % 50;
        const int kh = rem / 25, cell = rem % 25;
        const int v0 = (cell / 5) * 5, w0 = (cell % 5) * 5;
        int br1, gi, gj;
        if (pair < 4) { br1 = 2 * pair;          gi = c_gi9[pair];     gj = c_gj9[pair]; }
        else          { br1 = 8 + 2 * (pair - 4); gi = c_gi1[pair - 4]; gj = c_gj1[pair - 4]; }
        const __nv_bfloat16* f1 = fT + (size_t)(br1 * 25 + v0) * 132 + kh * 64;
        const __nv_bfloat16* f2 = fT + (size_t)((br1 + 1) * 25 + w0) * 132 + kh * 64;
        ull g[5][5];
#pragma unroll
        for (int r = 0; r < 5; ++r)
#pragma unroll
            for (int s = 0; s < 5; ++s) g[r][s] = 0ULL;
        for (int kp = 0; kp < 32; ++kp) {
            ull a[5], b[5];
#pragma unroll
            for (int r = 0; r < 5; ++r) {
                float2 fa = __bfloat1622float2(*(const __nv_bfloat162*)(f1 + r * 132 + kp * 2));
                a[r] = pack2(fa.x, fa.y);
            }
#pragma unroll
            for (int s = 0; s < 5; ++s) {
                float2 fb = __bfloat1622float2(*(const __nv_bfloat162*)(f2 + s * 132 + kp * 2));
                b[s] = pack2(fb.x, fb.y);
            }
#pragma unroll
            for (int r = 0; r < 5; ++r)
#pragma unroll
                for (int s = 0; s < 5; ++s) fma2(g[r][s], a[r], b[s]);
        }
        float* dst = g_Gram + ((size_t)(n * 3 + gi) * 3 + gj) * 625;
#pragma unroll
        for (int r = 0; r < 5; ++r)
#pragma unroll
            for (int s = 0; s < 5; ++s) {
                float2 f = unpack2(g[r][s]);
                atomicAdd(&dst[(v0 + r) * 25 + (w0 + s)], f.x + f.y);
            }
    }
}

// ---------------- kernel 2: softmax + combine into A1 ----------------------
__global__ void smx_kernel(const float* __restrict__ weights) {
    const int n = blockIdx.x, i = blockIdx.y, w = threadIdx.x;
    if (w >= 25) return;
    const float INV = 1.f / 4096.f;
    const float wj[3] = {weights[5], weights[6], weights[7]};
    float a1[25];
#pragma unroll
    for (int v = 0; v < 25; ++v) a1[v] = g_Acomb[v * 25 + w];
    for (int j = 0; j < 3; ++j) {
        const float* gb = g_Gram + ((size_t)(n * 3 + i) * 3 + j) * 625 + w;
        float m = -1e30f;
        for (int v = 0; v < 25; ++v) m = fmaxf(m, gb[v * 25] * INV);
        float s = 0.f;
        for (int v = 0; v < 25; ++v) s += expf(gb[v * 25] * INV - m);
        float inv = wj[j] / s;
        for (int v = 0; v < 25; ++v) a1[v] += inv * expf(gb[v * 25] * INV - m);
    }
    float* out = g_A1 + (size_t)(n * 3 + i) * 625 + w;
    for (int v = 0; v < 25; ++v) out[v * 25] = a1[v];
}

// ---------------- kernel 3: fused z = x@A1, Wd(BN-folded), residual, relu --
__global__ void __launch_bounds__(256) final_kernel(const float* __restrict__ x,
                                                    float* __restrict__ out) {
    extern __shared__ float sm[];
    float* w2s = sm;            // 12288
    float* xs  = sm + 12288;    // 1600
    float* A1s = sm + 13888;    // 1952
    float* zs  = sm + 15840;    // 6144
    const int t = blockIdx.x, n = blockIdx.y, tid = threadIdx.x;
    for (int idx = tid; idx < 12288; idx += 256) w2s[idx] = g_WdS[idx];
    const float* xb = x + ((size_t)n * CC * TT + t) * VV;
    for (int idx = tid; idx < 1600; idx += 256) {
        int c = idx / 25, v = idx % 25;
        xs[idx] = xb[(size_t)c * (TT * VV) + v];
    }
    for (int idx = tid; idx < 1950; idx += 256) {
        int row = idx / 26, w = idx % 26;
        A1s[idx] = (w < 25) ? g_A1[(size_t)n * 1875 + row * 25 + w] : 0.f;
    }
    for (int idx = tid; idx < 6144; idx += 256) zs[idx] = 0.f;
    __syncthreads();
    for (int idx = tid; idx < 2496; idx += 256) {
        int k = idx / 13, wp = idx % 13;
        int i = k / 64, c = k % 64;
        ull a = 0ULL;
        const float* xr = &xs[c * 25];
        const float* ar = &A1s[i * 650 + 2 * wp];
#pragma unroll
        for (int v = 0; v < 25; ++v) {
            float xv = xr[v];
            fma2(a, pack2(xv, xv), *(const ull*)&ar[v * 26]);
        }
        *(ull*)&zs[k * 32 + 2 * wp] = a;
    }
    __syncthreads();
    {
        const int o = tid & 63, vg = tid >> 6;
        ull a0 = 0, a1 = 0, a2 = 0, a3 = 0;
        const float* wcol = &w2s[o];
        const float* zrow = &zs[vg * 8];
#pragma unroll 8
        for (int k = 0; k < 192; ++k) {
            float wv = wcol[k * 64];
            ull wd = pack2(wv, wv);
            ulonglong2 z1 = *(const ulonglong2*)&zrow[k * 32];
            ulonglong2 z2 = *(const ulonglong2*)&zrow[k * 32 + 4];
            fma2(a0, wd, z1.x);
            fma2(a1, wd, z1.y);
            fma2(a2, wd, z2.x);
            fma2(a3, wd, z2.y);
        }
        const float bias = g_bd2[o];
        float* ob = out + ((size_t)(n * 64 + o) * TT + t) * VV;
        const float* xr = &xs[o * 25];
        ull accs[4] = {a0, a1, a2, a3};
#pragma unroll
        for (int j = 0; j < 4; ++j) {
            float2 f = unpack2(accs[j]);
            int v = vg * 8 + 2 * j;
            if (v < 25)     ob[v]     = fmaxf(f.x + bias + xr[v], 0.f);
            if (v + 1 < 25) ob[v + 1] = fmaxf(f.y + bias + xr[v + 1], 0.f);
        }
    }
}

// ---------------- launch ----------------------------------------------------
extern "C" void kernel_launch(void* const* d_in, const int* in_sizes, int n_in,
                              void* d_out, int out_size) {
    const float* x       = (const float*)d_in[0];
    const float* weights = (const float*)d_in[1];
    const float* A       = (const float*)d_in[2];
    const float* Wa      = (const float*)d_in[3];
    const float* ba      = (const float*)d_in[4];
    const float* Wb      = (const float*)d_in[5];
    const float* bb      = (const float*)d_in[6];
    const float* Wd      = (const float*)d_in[7];
    const float* bd      = (const float*)d_in[8];
    const float* WT1     = (const float*)d_in[9];
    const float* bT1     = (const float*)d_in[10];
    const float* WT2     = (const float*)d_in[11];
    const float* bT2     = (const float*)d_in[12];
    const float* WST11   = (const float*)d_in[13];
    const float* bST11   = (const float*)d_in[14];
    const float* WST12   = (const float*)d_in[15];
    const float* bST12   = (const float*)d_in[16];
    const float* bn_g    = (const float*)d_in[17];
    const float* bn_b    = (const float*)d_in[18];
    const float* bn_m    = (const float*)d_in[19];
    const float* bn_v    = (const float*)d_in[20];
    float* out = (float*)d_out;

    cudaFuncSetAttribute(convm_kernel, cudaFuncAttributeMaxDynamicSharedMemorySize, SMEM_CONV);
    cudaFuncSetAttribute(final_kernel, cudaFuncAttributeMaxDynamicSharedMemorySize, 87936);

    void* gram_ptr = nullptr;
    cudaGetSymbolAddress(&gram_ptr, g_Gram);

    prep_kernel<<<1, 640>>>(weights, A, Wa, ba, Wb, bb, WT1, bT1, WT2, bT2,
                            WST11, bST11, WST12, bST12, Wd, bd, bn_g, bn_b, bn_m, bn_v);
    cudaMemsetAsync(gram_ptr, 0, sizeof(float) * 64 * 9 * 625);
    convm_kernel<<<dim3(32, NB), 512, SMEM_CONV>>>(x);
    smx_kernel<<<dim3(NB, 3), 32>>>(weights);
    final_kernel<<<dim3(TT, NB), 256, 87936>>>(x, out);
}

// round 7
// speedup vs baseline: 1.2717x; 1.2717x over previous
#include <cuda_runtime.h>
#include <cuda_bf16.h>
#include <cstdint>

#define NB   64
#define CC   64
#define TT   256
#define VV   25

typedef unsigned long long ull;

// ---------------- scratch (static device memory) ----------------
__device__ __align__(16) __nv_bfloat16 g_W9b[9 * 128 * 64];  // [tap][ch][cin]
__device__ __align__(16) __nv_bfloat16 g_W1b[160 * 64];      // [ch][cin]
__device__ float g_b9[128];
__device__ float g_b1[160];
__device__ float g_Acomb[625];
__device__ float g_Gram[64 * 9 * 625];
__device__ float g_A1[64 * 3 * 625];
__device__ float g_WdS[192 * 64];
__device__ float g_bd2[64];

// branch tables
__constant__ int c_i9[8]  = {0,0,1,1,1,1,2,2};
__constant__ int c_s9[8]  = {0,1,0,1,2,3,0,1};
__constant__ int c_i1[10] = {0,0,0,0,1,1,2,2,2,2};
__constant__ int c_s1[10] = {0,1,2,3,0,1,0,1,2,3};
__constant__ int c_gi9[4] = {0,1,1,2};
__constant__ int c_gj9[4] = {1,1,2,1};
__constant__ int c_gi1[5] = {0,0,1,2,2};
__constant__ int c_gj1[5] = {0,2,0,0,2};

// ---------------- f32x2 helpers ----------------
__device__ __forceinline__ ull pack2(float lo, float hi) {
    ull r; asm("mov.b64 %0, {%1,%2};" : "=l"(r) : "f"(lo), "f"(hi)); return r;
}
__device__ __forceinline__ void fma2(ull& d, ull a, ull b) {
    asm("fma.rn.f32x2 %0, %1, %2, %0;" : "+l"(d) : "l"(a), "l"(b));
}
__device__ __forceinline__ float2 unpack2(ull p) {
    float2 f; asm("mov.b64 {%0,%1}, %2;" : "=f"(f.x), "=f"(f.y) : "l"(p)); return f;
}

// ---------------- mma.sync m16n8k16 bf16 (sm_80+, compute_103-safe) --------
__device__ __forceinline__ void mma_bf16(float* d, uint32_t a0, uint32_t a1,
                                         uint32_t a2, uint32_t a3,
                                         uint32_t b0, uint32_t b1) {
    asm volatile(
        "mma.sync.aligned.m16n8k16.row.col.f32.bf16.bf16.f32 "
        "{%0,%1,%2,%3}, {%4,%5,%6,%7}, {%8,%9}, {%0,%1,%2,%3};"
        : "+f"(d[0]), "+f"(d[1]), "+f"(d[2]), "+f"(d[3])
        : "r"(a0), "r"(a1), "r"(a2), "r"(a3), "r"(b0), "r"(b1));
}

// ---------------- kernel 0: prep ----------------
__global__ void prep_kernel(const float* __restrict__ weights, const float* __restrict__ A,
                            const float* __restrict__ Wa, const float* __restrict__ ba,
                            const float* __restrict__ Wb, const float* __restrict__ bb,
                            const float* __restrict__ WT1, const float* __restrict__ bT1,
                            const float* __restrict__ WT2, const float* __restrict__ bT2,
                            const float* __restrict__ WST11, const float* __restrict__ bST11,
                            const float* __restrict__ WST12, const float* __restrict__ bST12,
                            const float* __restrict__ Wd, const float* __restrict__ bd,
                            const float* __restrict__ gamma, const float* __restrict__ beta,
                            const float* __restrict__ mean, const float* __restrict__ var) {
    __shared__ float sA[625], sA4[625];
    const int tid = threadIdx.x;
    if (tid < 625) {
        float a = A[tid];
        sA[tid] = a;
        int v = tid / 25, w = tid % 25;
        float a2 = a * a;  // elementwise Chebyshev (torch.pow semantics)
        sA4[tid] = 8.f * a2 * a2 - 8.f * a2 + (v == w ? 1.f : 0.f);
    }
    __syncthreads();
    if (tid < 25) {
        const int w = tid;
        float w0 = weights[0], w1 = weights[1];
        float m = -1e30f;
        for (int v = 0; v < 25; ++v) m = fmaxf(m, sA4[v*25+w] * 0.04f);
        float ssum = 0.f;
        for (int v = 0; v < 25; ++v) ssum += expf(sA4[v*25+w] * 0.04f - m);
        float inv = 1.f / ssum;
        for (int v = 0; v < 25; ++v)
            g_Acomb[v*25+w] = w0 * sA[v*25+w] + w1 * expf(sA4[v*25+w] * 0.04f - m) * inv;
    }
    for (int idx = tid; idx < 9 * 128 * 64; idx += blockDim.x) {
        int tap = idx / 8192, r = idx % 8192;
        int m = r / 64, c = r % 64;
        int g = m >> 4;
        int i = c_i9[g], s = c_s9[g];
        const float* W = (s == 0) ? WT1 : (s == 1) ? WT2 : (s == 2) ? WST11 : WST12;
        g_W9b[idx] = __float2bfloat16(W[((i*16 + (m & 15))*64 + c)*9 + tap]);
    }
    for (int idx = tid; idx < 128; idx += blockDim.x) {
        int g = idx >> 4, c = idx & 15;
        int i = c_i9[g], s = c_s9[g];
        const float* B = (s == 0) ? bT1 : (s == 1) ? bT2 : (s == 2) ? bST11 : bST12;
        g_b9[idx] = B[i*16 + c];
    }
    for (int idx = tid; idx < 160 * 64; idx += blockDim.x) {
        int m = idx / 64, c = idx % 64;
        int g = m >> 4;
        int i = c_i1[g], s = c_s1[g];
        float val;
        if (s == 0)      val = Wa[(i*16 + (m & 15))*64 + c];
        else if (s == 1) val = Wb[(i*16 + (m & 15))*64 + c];
        else if (s == 2) val = WST11[((i*16 + (m & 15))*64 + c)*9 + 4];
        else             val = WST12[((i*16 + (m & 15))*64 + c)*9 + 4];
        g_W1b[idx] = __float2bfloat16(val);
    }
    for (int idx = tid; idx < 160; idx += blockDim.x) {
        int g = idx >> 4, c = idx & 15;
        int i = c_i1[g], s = c_s1[g];
        const float* B = (s == 0) ? ba : (s == 1) ? bb : (s == 2) ? bST11 : bST12;
        g_b1[idx] = B[i*16 + c];
    }
    for (int idx = tid; idx < 192 * 64; idx += blockDim.x) {
        int k = idx / 64, o = idx % 64;
        int i = k / 64, c = k % 64;
        float sc = gamma[o] * rsqrtf(var[o] + 1e-5f);
        g_WdS[idx] = Wd[(i * 64 + o) * 64 + c] * sc;
    }
    for (int o = tid; o < 64; o += blockDim.x) {
        float sc = gamma[o] * rsqrtf(var[o] + 1e-5f);
        g_bd2[o] = (bd[o] + bd[64 + o] + bd[128 + o] - mean[o]) * sc + beta[o];
    }
}

// ---------------- kernel 1: unified conv (mma.sync bf16) + fused gram ------
// grid (32 t-blocks of 8, 64 n), 512 thr = 16 warps.
// xs: [n=512 rows (16 tsl x 32 v)][72 cin-pad] bf16 -> 36-word stride:
//     bank = (4r + q) % 32 over the (r = lane>>2, q = lane&3) pattern = bijection
//     => conflict-free B-fragment LDS.
// fT: [18 br][25 v][132 kpad] bf16, k = (ch%16)*8 + tt
#define XS_N_STRIDE 72
#define XS_BF16     (512 * XS_N_STRIDE)            // 36864
#define FT_BF16     (18 * 25 * 132)                // 59400
#define SMEM_CONV   ((XS_BF16 + FT_BF16) * 2)      // 192528 B

__global__ void __launch_bounds__(512, 1) convm_kernel(const float* __restrict__ x) {
    extern __shared__ __nv_bfloat16 smb[];
    __nv_bfloat16* xs = smb;
    __nv_bfloat16* fT = smb + XS_BF16;
    const int n = blockIdx.y, t0 = blockIdx.x * 8;
    const int tid = threadIdx.x, warp = tid >> 5, lane = tid & 31;

    {
        uint32_t* xz = (uint32_t*)xs;
        for (int i = tid; i < XS_BF16 / 2; i += 512) xz[i] = 0u;
    }
    __syncthreads();
    {
        const float* xn = x + (size_t)n * (CC * TT * VV);
        for (int idx = tid; idx < 64 * 16 * 25; idx += 512) {
            int cin = idx / 400, r = idx % 400;
            int tsl = r / 25, v = r % 25;
            int t = t0 - 4 + tsl;
            if (t < 0 || t >= TT) continue;
            xs[(tsl * 32 + v) * XS_N_STRIDE + cin] =
                __float2bfloat16(xn[(cin * TT + t) * VV + v]);
        }
    }
    __syncthreads();

    const int row = lane >> 2;
    const int kq  = (lane & 3) * 2;
    float acc[16][4];

    for (int job = 0; job < 3; ++job) {
        if (job == 2 && warp >= 4) break;
        const int strip = (job == 0) ? (warp >> 1) : (job == 1) ? 8 + (warp >> 1)
                                                                : 16 + (warp >> 1);
        const int half = warp & 1;
        const int is9 = (job == 0);
#pragma unroll
        for (int a = 0; a < 16; ++a)
#pragma unroll
            for (int b = 0; b < 4; ++b) acc[a][b] = 0.f;

        const int ntaps = is9 ? 9 : 1;
        for (int jt = 0; jt < ntaps; ++jt) {
            const int tap = is9 ? jt : 4;
            const __nv_bfloat16* Ab = is9 ? g_W9b + (size_t)(tap * 128 + strip * 16) * 64
                                          : g_W1b + (size_t)(strip - 8) * 16 * 64;
            const __nv_bfloat16* xb = xs + (size_t)(tap * 32 + half * 128 + row) * XS_N_STRIDE;
#pragma unroll
            for (int k0 = 0; k0 < 64; k0 += 16) {
                uint32_t a0 = *(const uint32_t*)(Ab + row * 64 + k0 + kq);
                uint32_t a1 = *(const uint32_t*)(Ab + (row + 8) * 64 + k0 + kq);
                uint32_t a2 = *(const uint32_t*)(Ab + row * 64 + k0 + kq + 8);
                uint32_t a3 = *(const uint32_t*)(Ab + (row + 8) * 64 + k0 + kq + 8);
#pragma unroll
                for (int nt = 0; nt < 16; ++nt) {
                    uint32_t b0 = *(const uint32_t*)(xb + nt * 8 * XS_N_STRIDE + k0 + kq);
                    uint32_t b1 = *(const uint32_t*)(xb + nt * 8 * XS_N_STRIDE + k0 + kq + 8);
                    mma_bf16(acc[nt], a0, a1, a2, a3, b0, b1);
                }
            }
        }
        const float* bias_arr = is9 ? g_b9 + strip * 16 : g_b1 + (strip - 8) * 16;
        const float bias_lo = bias_arr[row];
        const float bias_hi = bias_arr[row + 8];
#pragma unroll
        for (int nt = 0; nt < 16; ++nt)
#pragma unroll
            for (int j = 0; j < 4; ++j) {
                const int ch = row + ((j >= 2) ? 8 : 0);
                const int nl = half * 128 + nt * 8 + (lane & 3) * 2 + (j & 1);
                const int tt = nl >> 5, v = nl & 31;
                if (v < 25)
                    fT[(strip * 25 + v) * 132 + ch * 8 + tt] =
                        __float2bfloat16(acc[nt][j] + ((j >= 2) ? bias_hi : bias_lo));
            }
    }
    __syncthreads();

    // gram: 450 workers = 9 pairs x 25 cells x 2 k-halves (k=64 each)
    if (tid < 450) {
        const int pair = tid / 50, rem = tid % 50;
        const int kh = rem / 25, cell = rem % 25;
        const int v0 = (cell / 5) * 5, w0 = (cell % 5) * 5;
        int br1, gi, gj;
        if (pair < 4) { br1 = 2 * pair;           gi = c_gi9[pair];      gj = c_gj9[pair]; }
        else          { br1 = 8 + 2 * (pair - 4); gi = c_gi1[pair - 4];  gj = c_gj1[pair - 4]; }
        const __nv_bfloat16* f1 = fT + (size_t)(br1 * 25 + v0) * 132 + kh * 64;
        const __nv_bfloat16* f2 = fT + (size_t)((br1 + 1) * 25 + w0) * 132 + kh * 64;
        ull g[5][5];
#pragma unroll
        for (int r = 0; r < 5; ++r)
#pragma unroll
            for (int s = 0; s < 5; ++s) g[r][s] = 0ULL;
        for (int kp = 0; kp < 32; ++kp) {
            ull a[5], b[5];
#pragma unroll
            for (int r = 0; r < 5; ++r) {
                float2 fa = __bfloat1622float2(*(const __nv_bfloat162*)(f1 + r * 132 + kp * 2));
                a[r] = pack2(fa.x, fa.y);
            }
#pragma unroll
            for (int s = 0; s < 5; ++s) {
                float2 fb = __bfloat1622float2(*(const __nv_bfloat162*)(f2 + s * 132 + kp * 2));
                b[s] = pack2(fb.x, fb.y);
            }
#pragma unroll
            for (int r = 0; r < 5; ++r)
#pragma unroll
                for (int s = 0; s < 5; ++s) fma2(g[r][s], a[r], b[s]);
        }
        float* dst = g_Gram + ((size_t)(n * 3 + gi) * 3 + gj) * 625;
#pragma unroll
        for (int r = 0; r < 5; ++r)
#pragma unroll
            for (int s = 0; s < 5; ++s) {
                float2 f = unpack2(g[r][s]);
                atomicAdd(&dst[(v0 + r) * 25 + (w0 + s)], f.x + f.y);
            }
    }
}

// ---------------- kernel 2: softmax + combine into A1 ----------------------
__global__ void smx_kernel(const float* __restrict__ weights) {
    const int n = blockIdx.x, i = blockIdx.y, w = threadIdx.x;
    if (w >= 25) return;
    const float INV = 1.f / 4096.f;
    const float wj[3] = {weights[5], weights[6], weights[7]};
    float a1[25];
#pragma unroll
    for (int v = 0; v < 25; ++v) a1[v] = g_Acomb[v * 25 + w];
    for (int j = 0; j < 3; ++j) {
        const float* gb = g_Gram + ((size_t)(n * 3 + i) * 3 + j) * 625 + w;
        float m = -1e30f;
        for (int v = 0; v < 25; ++v) m = fmaxf(m, gb[v * 25] * INV);
        float s = 0.f;
        for (int v = 0; v < 25; ++v) s += expf(gb[v * 25] * INV - m);
        float inv = wj[j] / s;
        for (int v = 0; v < 25; ++v) a1[v] += inv * expf(gb[v * 25] * INV - m);
    }
    float* out = g_A1 + (size_t)(n * 3 + i) * 625 + w;
    for (int v = 0; v < 25; ++v) out[v * 25] = a1[v];
}

// ---------------- kernel 3: fused z = x@A1, Wd(BN-folded), residual, relu --
// grid (T/4, N), 256 thr; 4 t-steps per block amortize the 48KB Wd table.
__global__ void __launch_bounds__(256) final_kernel(const float* __restrict__ x,
                                                    float* __restrict__ out) {
    extern __shared__ float sm[];
    float* w2s = sm;            // 12288
    float* xs  = sm + 12288;    // 1600
    float* A1s = sm + 13888;    // 1952
    float* zs  = sm + 15840;    // 6144
    const int tb = blockIdx.x, n = blockIdx.y, tid = threadIdx.x;
    for (int idx = tid; idx < 12288; idx += 256) w2s[idx] = g_WdS[idx];
    for (int idx = tid; idx < 1950; idx += 256) {
        int row = idx / 26, w = idx % 26;
        A1s[idx] = (w < 25) ? g_A1[(size_t)n * 1875 + row * 25 + w] : 0.f;
    }
    for (int idx = tid; idx < 6144; idx += 256) zs[idx] = 0.f;

    for (int ts = 0; ts < 4; ++ts) {
        const int t = tb * 4 + ts;
        const float* xb = x + ((size_t)n * CC * TT + t) * VV;
        for (int idx = tid; idx < 1600; idx += 256) {
            int c = idx / 25, v = idx % 25;
            xs[idx] = xb[(size_t)c * (TT * VV) + v];
        }
        __syncthreads();
        // stage B: z[k=(i,c)][w-pair] via f32x2
        for (int idx = tid; idx < 2496; idx += 256) {
            int k = idx / 13, wp = idx % 13;
            int i = k / 64, c = k % 64;
            ull a = 0ULL;
            const float* xr = &xs[c * 25];
            const float* ar = &A1s[i * 650 + 2 * wp];
#pragma unroll
            for (int v = 0; v < 25; ++v) {
                float xv = xr[v];
                fma2(a, pack2(xv, xv), *(const ull*)&ar[v * 26]);
            }
            *(ull*)&zs[k * 32 + 2 * wp] = a;
        }
        __syncthreads();
        // stage C
        {
            const int o = tid & 63, vg = tid >> 6;
            ull a0 = 0, a1 = 0, a2 = 0, a3 = 0;
            const float* wcol = &w2s[o];
            const float* zrow = &zs[vg * 8];
#pragma unroll 8
            for (int k = 0; k < 192; ++k) {
                float wv = wcol[k * 64];
                ull wd = pack2(wv, wv);
                ulonglong2 z1 = *(const ulonglong2*)&zrow[k * 32];
                ulonglong2 z2 = *(const ulonglong2*)&zrow[k * 32 + 4];
                fma2(a0, wd, z1.x);
                fma2(a1, wd, z1.y);
                fma2(a2, wd, z2.x);
                fma2(a3, wd, z2.y);
            }
            const float bias = g_bd2[o];
            float* ob = out + ((size_t)(n * 64 + o) * TT + t) * VV;
            const float* xr = &xs[o * 25];
            ull accs[4] = {a0, a1, a2, a3};
#pragma unroll
            for (int j = 0; j < 4; ++j) {
                float2 f = unpack2(accs[j]);
                int v = vg * 8 + 2 * j;
                if (v < 25)     ob[v]     = fmaxf(f.x + bias + xr[v], 0.f);
                if (v + 1 < 25) ob[v + 1] = fmaxf(f.y + bias + xr[v + 1], 0.f);
            }
        }
        __syncthreads();
    }
}

// ---------------- launch ----------------------------------------------------
extern "C" void kernel_launch(void* const* d_in, const int* in_sizes, int n_in,
                              void* d_out, int out_size) {
    const float* x       = (const float*)d_in[0];
    const float* weights = (const float*)d_in[1];
    const float* A       = (const float*)d_in[2];
    const float* Wa      = (const float*)d_in[3];
    const float* ba      = (const float*)d_in[4];
    const float* Wb      = (const float*)d_in[5];
    const float* bb      = (const float*)d_in[6];
    const float* Wd      = (const float*)d_in[7];
    const float* bd      = (const float*)d_in[8];
    const float* WT1     = (const float*)d_in[9];
    const float* bT1     = (const float*)d_in[10];
    const float* WT2     = (const float*)d_in[11];
    const float* bT2     = (const float*)d_in[12];
    const float* WST11   = (const float*)d_in[13];
    const float* bST11   = (const float*)d_in[14];
    const float* WST12   = (const float*)d_in[15];
    const float* bST12   = (const float*)d_in[16];
    const float* bn_g    = (const float*)d_in[17];
    const float* bn_b    = (const float*)d_in[18];
    const float* bn_m    = (const float*)d_in[19];
    const float* bn_v    = (const float*)d_in[20];
    float* out = (float*)d_out;

    cudaFuncSetAttribute(convm_kernel, cudaFuncAttributeMaxDynamicSharedMemorySize, SMEM_CONV);
    cudaFuncSetAttribute(final_kernel, cudaFuncAttributeMaxDynamicSharedMemorySize, 87936);

    void* gram_ptr = nullptr;
    cudaGetSymbolAddress(&gram_ptr, g_Gram);

    prep_kernel<<<1, 640>>>(weights, A, Wa, ba, Wb, bb, WT1, bT1, WT2, bT2,
                            WST11, bST11, WST12, bST12, Wd, bd, bn_g, bn_b, bn_m, bn_v);
    cudaMemsetAsync(gram_ptr, 0, sizeof(float) * 64 * 9 * 625);
    convm_kernel<<<dim3(32, NB), 512, SMEM_CONV>>>(x);
    smx_kernel<<<dim3(NB, 3), 32>>>(weights);
    final_kernel<<<dim3(TT / 4, NB), 256, 87936>>>(x, out);
}